// round 17
// baseline (speedup 1.0000x reference)
#include <cuda_runtime.h>
#include <cuda_fp16.h>
#include <stdint.h>

// MultiLevelSparseHashEncoding — round 17.
// R16: out-T pinned at ~31us / 58% DRAM regardless of MLP & occupancy ->
// it's at its traffic ceiling; main (~64us) is at its gather floor.
// Remaining win is OVERLAP: main is L1-bound (DRAM 10%), out-T DRAM-bound.
// Split into 4 chunks; capture-stream runs main(c0..c3) back-to-back, a
// second stream runs outT(c) after an event from main(c).  Graph gets
// parallel branches: outT(c) overlaps main(c+1).  Co-residency fits
// (131KB + 2x33KB SMEM, 1024+512 threads).  Kernel math identical to R16.

#define NLVL 16
#define NENC 16384
#define NPTS (1 << 20)
#define TPB  1024
#define NPAIR 8
#define NSLICE 19
#define NCHUNK 4
#define CHUNK (NPTS / NCHUNK)                      // 262144
#define SLICE_C 13800                              // mult of 4; 19*13800 >= CHUNK
#define SMEM_BYTES ((2 * (NENC + 1)) * (int)sizeof(__half2))   // 131080
#define SCALE    4096.0f
#define INV_SCALE (1.0f / 4096.0f)

__constant__ int c_res[NLVL] = {16, 20, 25, 32, 40, 50, 64, 80,
                                101, 128, 161, 203, 256, 322, 406, 512};
__constant__ int c_nle[NLVL] = {4096, 8000, 15625, 16384, 16384, 16384,
                                16384, 16384, 16384, 16384, 16384, 16384,
                                16384, 16384, 16384, 16384};

__device__ uint2 g_stage[(size_t)NPAIR * NPTS];    // [pair][point] half4 bits

// ---------------------------------------------------------------- per-level
template <bool DIRECT>
__device__ __forceinline__ __half2
level_feat(const __half2* __restrict__ tab, const int R,
           const float xv0, const float xv1, const float xv2)
{
    const float halfR = 0.5f * (float)R;
    const float cadd  = halfR - 0.5f;
    const float t0 = fmaf(xv0, halfR, cadd);
    const float t1 = fmaf(xv1, halfR, cadd);
    const float t2 = fmaf(xv2, halfR, cadd);

    const float fl0 = floorf(t0), fl1 = floorf(t1), fl2 = floorf(t2);
    const float fr0 = t0 - fl0, fr1 = t1 - fl1, fr2 = t2 - fl2;
    const int   i0  = (int)fl0, i1 = (int)fl1, i2 = (int)fl2;

    const float wx0 = i0     >= 0 ? 1.0f - fr0 : 0.0f;
    const float wx1 = i0 + 1 <  R ? fr0        : 0.0f;
    const float wy0 = i1     >= 0 ? 1.0f - fr1 : 0.0f;
    const float wy1 = i1 + 1 <  R ? fr1        : 0.0f;
    const float wz[2] = {i2     >= 0 ? 1.0f - fr2 : 0.0f,
                         i2 + 1 <  R ? fr2        : 0.0f};
    const float wxy[4] = {wx0 * wy0, wx0 * wy1, wx1 * wy0, wx1 * wy1};

    unsigned kx[2], kyz[4];
    if (DIRECT) {
        const int R2 = R * R;
        const int a0 = max(i0, 0), a1 = min(i0 + 1, R - 1);
        const int b0 = max(i1, 0), b1 = min(i1 + 1, R - 1);
        const int d0 = max(i2, 0), d1 = min(i2 + 1, R - 1);
        kx[0] = (unsigned)(a0 * R2); kx[1] = (unsigned)(a1 * R2);
        kyz[0] = (unsigned)(b0 * R + d0); kyz[1] = (unsigned)(b0 * R + d1);
        kyz[2] = (unsigned)(b1 * R + d0); kyz[3] = (unsigned)(b1 * R + d1);
    } else {
        kx[0] = (unsigned)i0; kx[1] = (unsigned)(i0 + 1);
        const unsigned hy0 = (unsigned)i1 * 2654435761u;
        const unsigned hy1 = hy0 + 2654435761u;
        const unsigned hz0 = (unsigned)i2 * 805459861u;
        const unsigned hz1 = hz0 + 805459861u;
        kyz[0] = hy0 ^ hz0; kyz[1] = hy0 ^ hz1;
        kyz[2] = hy1 ^ hz0; kyz[3] = hy1 ^ hz1;
    }
    const unsigned mask = NENC - 1;

    __half2 acc = __float2half2_rn(0.0f);
    #pragma unroll
    for (int c = 0; c < 8; ++c) {
        const int ox = (c >> 2) & 1, oyz = c & 3;
        unsigned id;
        if (DIRECT) id = kx[ox] + kyz[oyz];
        else        id = (kx[ox] ^ kyz[oyz]) & mask;
        const float   w  = wxy[2 * ox + (oyz >> 1)] * wz[oyz & 1];
        const __half2 w2 = __float2half2_rn(w);
        acc = __hfma2(w2, tab[id], acc);
    }
    return acc;
}

// ---------------------------------------------------------------- main
__global__ __launch_bounds__(TPB, 1)
void hashgrid_pair_kernel(const float* __restrict__ emb,
                          const float4* __restrict__ x4,
                          const int pbase)
{
    extern __shared__ __half2 tab[];

    const int m     = blockIdx.x & (NPAIR - 1);
    const int slice = blockIdx.x >> 3;
    const int lA = 2 * m, lB = 2 * m + 1;
    const int RA = c_res[lA], RB = c_res[lB];
    const int neA = c_nle[lA], neB = c_nle[lB];

    __half2* tabA = tab;
    __half2* tabB = tab + (neA + 1);

    const float2* __restrict__ srcA =
        reinterpret_cast<const float2*>(emb) + (size_t)lA * (NENC + 1);
    const float2* __restrict__ srcB =
        reinterpret_cast<const float2*>(emb) + (size_t)lB * (NENC + 1);
    for (int i = threadIdx.x; i <= neA; i += TPB) {
        const float2 v = srcA[i];
        tabA[i] = __floats2half2_rn(v.x * SCALE, v.y * SCALE);
    }
    for (int i = threadIdx.x; i <= neB; i += TPB) {
        const float2 v = srcB[i];
        tabB[i] = __floats2half2_rn(v.x * SCALE, v.y * SCALE);
    }
    __syncthreads();

    uint4* __restrict__ stage4 =
        reinterpret_cast<uint4*>(g_stage + (size_t)m * NPTS);

    const int base4 = (pbase + slice * SLICE_C) / 4;
    const int end4  = min(pbase + (slice + 1) * SLICE_C, pbase + CHUNK) / 4;
    #pragma unroll 1
    for (int i = base4 + threadIdx.x; i < end4; i += TPB) {
        const float4 a = x4[3 * i + 0];
        const float4 b = x4[3 * i + 1];
        const float4 c = x4[3 * i + 2];
        const float px[4] = {a.x, a.w, b.z, c.y};
        const float py[4] = {a.y, b.x, b.w, c.z};
        const float pz[4] = {a.z, b.y, c.x, c.w};

        unsigned r[8];
        #pragma unroll
        for (int k = 0; k < 4; ++k) {
            __half2 rA, rB;
            if (lA < 3) rA = level_feat<true >(tabA, RA, px[k], py[k], pz[k]);
            else        rA = level_feat<false>(tabA, RA, px[k], py[k], pz[k]);
            if (lB < 3) rB = level_feat<true >(tabB, RB, px[k], py[k], pz[k]);
            else        rB = level_feat<false>(tabB, RB, px[k], py[k], pz[k]);
            r[2 * k]     = *reinterpret_cast<unsigned*>(&rA);
            r[2 * k + 1] = *reinterpret_cast<unsigned*>(&rB);
        }
        stage4[2 * i]     = make_uint4(r[0], r[1], r[2], r[3]);
        stage4[2 * i + 1] = make_uint4(r[4], r[5], r[6], r[7]);
    }
}

// ---------------------------------------------------------------- transpose
#define TPB3 256
#define PPT  512
__global__ __launch_bounds__(TPB3)
void transpose_out_kernel(float4* __restrict__ out, const int pbase)
{
    __shared__ uint2 arr[NPAIR][PPT + 2];

    const int base = pbase + blockIdx.x * PPT;
    const int tid  = threadIdx.x;

    const uint4* __restrict__ st4 = reinterpret_cast<const uint4*>(g_stage);
    #pragma unroll
    for (int m = 0; m < NPAIR; ++m) {
        const uint4 v = __ldcs(&st4[((size_t)m * NPTS + base) / 2 + tid]);
        *reinterpret_cast<uint4*>(&arr[m][2 * tid]) = v;
    }
    __syncthreads();

    #pragma unroll
    for (int k = 0; k < 16; ++k) {
        const int local = k * TPB3 + tid;
        const int p_off = local >> 3;
        const int m     = local & 7;
        const uint2 v = arr[m][p_off];
        const float2 fa = __half22float2(*reinterpret_cast<const __half2*>(&v.x));
        const float2 fb = __half22float2(*reinterpret_cast<const __half2*>(&v.y));
        out[(size_t)base * 8 + local] =
            make_float4(fa.x * INV_SCALE, fa.y * INV_SCALE,
                        fb.x * INV_SCALE, fb.y * INV_SCALE);
    }
}

// ---------------------------------------------------------------- launch
extern "C" void kernel_launch(void* const* d_in, const int* in_sizes, int n_in,
                              void* d_out, int out_size)
{
    (void)n_in; (void)out_size;
    const float* x;
    const float* emb;
    if (in_sizes[0] == 3 * NPTS) { x = (const float*)d_in[0]; emb = (const float*)d_in[1]; }
    else                         { x = (const float*)d_in[1]; emb = (const float*)d_in[0]; }
    float4* out = (float4*)d_out;

    // one-time resource setup (first call is the uncaptured correctness run)
    static cudaStream_t s2 = nullptr;
    static cudaEvent_t  evM[NCHUNK];
    static cudaEvent_t  evFork, evJoin;
    if (s2 == nullptr) {
        cudaStreamCreateWithFlags(&s2, cudaStreamNonBlocking);
        cudaEventCreateWithFlags(&evFork, cudaEventDisableTiming);
        cudaEventCreateWithFlags(&evJoin, cudaEventDisableTiming);
        for (int c = 0; c < NCHUNK; ++c)
            cudaEventCreateWithFlags(&evM[c], cudaEventDisableTiming);
        cudaFuncSetAttribute(hashgrid_pair_kernel,
                             cudaFuncAttributeMaxDynamicSharedMemorySize,
                             SMEM_BYTES);
    }

    const float4* x4 = reinterpret_cast<const float4*>(x);

    // fork s2 from the capture stream
    cudaEventRecord(evFork, 0);
    cudaStreamWaitEvent(s2, evFork, 0);

    for (int c = 0; c < NCHUNK; ++c) {
        hashgrid_pair_kernel<<<NPAIR * NSLICE, TPB, SMEM_BYTES>>>(
            emb, x4, c * CHUNK);
        cudaEventRecord(evM[c], 0);
        cudaStreamWaitEvent(s2, evM[c], 0);
        transpose_out_kernel<<<CHUNK / PPT, TPB3, 0, s2>>>(out, c * CHUNK);
    }

    // join s2 back into the capture stream
    cudaEventRecord(evJoin, s2);
    cudaStreamWaitEvent(0, evJoin, 0);
}